// round 1
// baseline (speedup 1.0000x reference)
#include <cuda_runtime.h>
#include <math.h>

// Problem constants
#define NSLICE 16      // B*Q = 2*8
#define LSEQ   2048
#define DLLM   768
#define EDIM   64
#define EPS    1e-5f

// Scratch (no cudaMalloc allowed)
__device__ float g_q[NSLICE * LSEQ * EDIM];
__device__ float g_k[NSLICE * LSEQ * EDIM];
__device__ float g_v[NSLICE * LSEQ * EDIM];
__device__ float g_o[NSLICE * LSEQ * EDIM];
__device__ float2 g_part[NSLICE * 32];   // per-CTA (sum, sumsq) partials
__device__ float2 g_stats[NSLICE];       // (mu, inv_std)

// ----------------------------------------------------------------------------
// Kernel 1: projection GEMM  Y[s] = X[s] @ W + b
// X: [NSLICE, LSEQ, DLLM], W: [DLLM, EDIM], Y: [NSLICE, LSEQ, EDIM]
// Tile: 128 rows x 64 cols, BK=32. Block 16x16, each thread 8x4 outputs.
// ----------------------------------------------------------------------------
__global__ void proj_kernel(const float* __restrict__ X,
                            const float* __restrict__ W,
                            const float* __restrict__ b,
                            int which)
{
    __shared__ float As[32][129];   // [k][row], pad 129 -> conflict-free col writes
    __shared__ float Bs[32][64];    // [k][col]

    float* Y = (which == 0) ? g_q : (which == 1) ? g_k : g_v;

    const int s    = blockIdx.y;
    const int row0 = blockIdx.x * 128;
    const int tx = threadIdx.x, ty = threadIdx.y;
    const int tid = ty * 16 + tx;

    const float* Xs = X + (size_t)s * LSEQ * DLLM + (size_t)row0 * DLLM;

    float acc[8][4];
    #pragma unroll
    for (int i = 0; i < 8; ++i)
        #pragma unroll
        for (int j = 0; j < 4; ++j) acc[i][j] = 0.f;

    for (int k0 = 0; k0 < DLLM; k0 += 32) {
        // Load A tile: 128 rows x 32 k (coalesced 128B per warp)
        #pragma unroll
        for (int t = 0; t < 16; ++t) {
            int idx = tid + t * 256;          // 0..4095
            int r  = idx >> 5;
            int kk = idx & 31;
            As[kk][r] = Xs[(size_t)r * DLLM + k0 + kk];
        }
        // Load B tile: 32 k x 64 cols
        #pragma unroll
        for (int t = 0; t < 8; ++t) {
            int idx = tid + t * 256;          // 0..2047
            int kk = idx >> 6;
            int c  = idx & 63;
            Bs[kk][c] = W[(size_t)(k0 + kk) * EDIM + c];
        }
        __syncthreads();

        #pragma unroll
        for (int kk = 0; kk < 32; ++kk) {
            float bcol[4];
            #pragma unroll
            for (int j = 0; j < 4; ++j) bcol[j] = Bs[kk][tx * 4 + j];
            #pragma unroll
            for (int i = 0; i < 8; ++i) {
                float a = As[kk][ty * 8 + i];
                #pragma unroll
                for (int j = 0; j < 4; ++j) acc[i][j] += a * bcol[j];
            }
        }
        __syncthreads();
    }

    float bb[4];
    #pragma unroll
    for (int j = 0; j < 4; ++j) bb[j] = b[tx * 4 + j];

    float* Ys = Y + (size_t)s * LSEQ * EDIM + (size_t)row0 * EDIM;
    #pragma unroll
    for (int i = 0; i < 8; ++i)
        #pragma unroll
        for (int j = 0; j < 4; ++j)
            Ys[(size_t)(ty * 8 + i) * EDIM + tx * 4 + j] = acc[i][j] + bb[j];
}

// ----------------------------------------------------------------------------
// Kernel 2: flash attention per 64-row query tile, online softmax, writes g_o
// plus per-CTA (sum, sumsq) partials for the InstanceNorm.
// Block 16x16 = 256 threads; thread (ty,tx) owns a 4x4 fragment.
// Dynamic SMEM: Qs[64][64], Ks[64][65], Vs[64][64], Ps[64][64]
// ----------------------------------------------------------------------------
#define KPAD 65
__global__ void attn_kernel()
{
    extern __shared__ float sm[];
    float* Qs = sm;                         // 64*64
    float* Ks = Qs + 64 * 64;               // 64*65 (padded: column-style reads)
    float* Vs = Ks + 64 * KPAD;             // 64*64
    float* Ps = Vs + 64 * 64;               // 64*64

    __shared__ float red[256];
    __shared__ float red2[256];

    const int s    = blockIdx.y;
    const int row0 = blockIdx.x * 64;
    const int tx = threadIdx.x, ty = threadIdx.y;
    const int tid = ty * 16 + tx;

    const float* Qg = g_q + (size_t)s * LSEQ * EDIM + (size_t)row0 * EDIM;
    const float* Kg = g_k + (size_t)s * LSEQ * EDIM;
    const float* Vg = g_v + (size_t)s * LSEQ * EDIM;

    // Load Q tile once
    #pragma unroll
    for (int t = 0; t < 16; ++t) {
        int idx = tid + t * 256;
        int r = idx >> 6, c = idx & 63;
        Qs[r * 64 + c] = Qg[(size_t)r * EDIM + c];
    }

    float m[4], l[4], O[4][4];
    #pragma unroll
    for (int i = 0; i < 4; ++i) {
        m[i] = -1e30f; l[i] = 0.f;
        #pragma unroll
        for (int j = 0; j < 4; ++j) O[i][j] = 0.f;
    }
    const float scale = 0.125f;   // 1/sqrt(64)

    for (int kt = 0; kt < LSEQ / 64; ++kt) {
        __syncthreads();   // protect Ks/Vs (+Qs first iter) from in-flight reads
        #pragma unroll
        for (int t = 0; t < 16; ++t) {
            int idx = tid + t * 256;
            int r = idx >> 6, c = idx & 63;
            Ks[r * KPAD + c] = Kg[(size_t)(kt * 64 + r) * EDIM + c];
            Vs[r * 64 + c]   = Vg[(size_t)(kt * 64 + r) * EDIM + c];
        }
        __syncthreads();

        // S = Q @ K^T  (64x64 tile)
        float sacc[4][4];
        #pragma unroll
        for (int i = 0; i < 4; ++i)
            #pragma unroll
            for (int j = 0; j < 4; ++j) sacc[i][j] = 0.f;

        #pragma unroll 8
        for (int e = 0; e < 64; ++e) {
            float qv[4], kv[4];
            #pragma unroll
            for (int i = 0; i < 4; ++i) qv[i] = Qs[(ty * 4 + i) * 64 + e];
            #pragma unroll
            for (int j = 0; j < 4; ++j) kv[j] = Ks[(tx * 4 + j) * KPAD + e];
            #pragma unroll
            for (int i = 0; i < 4; ++i)
                #pragma unroll
                for (int j = 0; j < 4; ++j) sacc[i][j] += qv[i] * kv[j];
        }

        // Online softmax (row groups are the 16 same-ty lanes of a half-warp)
        #pragma unroll
        for (int i = 0; i < 4; ++i) {
            float rmax = sacc[i][0];
            #pragma unroll
            for (int j = 1; j < 4; ++j) rmax = fmaxf(rmax, sacc[i][j]);
            #pragma unroll
            for (int off = 8; off; off >>= 1)
                rmax = fmaxf(rmax, __shfl_xor_sync(0xffffffffu, rmax, off));

            float mn = fmaxf(m[i], scale * rmax);
            float alpha = __expf(m[i] - mn);
            float rsum = 0.f;
            #pragma unroll
            for (int j = 0; j < 4; ++j) {
                float p = __expf(scale * sacc[i][j] - mn);
                sacc[i][j] = p;
                rsum += p;
            }
            #pragma unroll
            for (int off = 8; off; off >>= 1)
                rsum += __shfl_xor_sync(0xffffffffu, rsum, off);

            l[i] = l[i] * alpha + rsum;
            m[i] = mn;
            #pragma unroll
            for (int j = 0; j < 4; ++j) O[i][j] *= alpha;
        }

        // P to smem, then O += P @ V
        #pragma unroll
        for (int i = 0; i < 4; ++i)
            #pragma unroll
            for (int j = 0; j < 4; ++j)
                Ps[(ty * 4 + i) * 64 + (tx * 4 + j)] = sacc[i][j];
        __syncthreads();

        #pragma unroll 8
        for (int mi = 0; mi < 64; ++mi) {
            float pv[4], vv[4];
            #pragma unroll
            for (int i = 0; i < 4; ++i) pv[i] = Ps[(ty * 4 + i) * 64 + mi];
            #pragma unroll
            for (int j = 0; j < 4; ++j) vv[j] = Vs[mi * 64 + (tx * 4 + j)];
            #pragma unroll
            for (int i = 0; i < 4; ++i)
                #pragma unroll
                for (int j = 0; j < 4; ++j) O[i][j] += pv[i] * vv[j];
        }
    }

    // Finalize rows, write g_o, accumulate instance-norm partials
    float lsum = 0.f, lsq = 0.f;
    float* Og = g_o + (size_t)s * LSEQ * EDIM + (size_t)row0 * EDIM;
    #pragma unroll
    for (int i = 0; i < 4; ++i) {
        float inv = 1.f / l[i];
        #pragma unroll
        for (int j = 0; j < 4; ++j) {
            float o = O[i][j] * inv;
            Og[(size_t)(ty * 4 + i) * EDIM + tx * 4 + j] = o;
            lsum += o;
            lsq  += o * o;
        }
    }

    red[tid]  = lsum;
    red2[tid] = lsq;
    __syncthreads();
    #pragma unroll
    for (int st = 128; st; st >>= 1) {
        if (tid < st) { red[tid] += red[tid + st]; red2[tid] += red2[tid + st]; }
        __syncthreads();
    }
    if (tid == 0) g_part[s * 32 + blockIdx.x] = make_float2(red[0], red2[0]);
}

// ----------------------------------------------------------------------------
// Kernel 3: per-slice stats (16 blocks x 32 threads)
// ----------------------------------------------------------------------------
__global__ void stats_kernel()
{
    const int s = blockIdx.x;
    const int t = threadIdx.x;
    float2 p = g_part[s * 32 + t];
    float sum = p.x, sq = p.y;
    #pragma unroll
    for (int off = 16; off; off >>= 1) {
        sum += __shfl_xor_sync(0xffffffffu, sum, off);
        sq  += __shfl_xor_sync(0xffffffffu, sq,  off);
    }
    if (t == 0) {
        const float n = (float)(LSEQ * EDIM);
        float mu  = sum / n;
        float var = sq / n - mu * mu;
        g_stats[s] = make_float2(mu, rsqrtf(var + EPS));
    }
}

// ----------------------------------------------------------------------------
// Kernel 4: normalize into d_out
// ----------------------------------------------------------------------------
__global__ void norm_kernel(float* __restrict__ out)
{
    int idx4 = blockIdx.x * 256 + threadIdx.x;      // element-group of 4
    int base = idx4 * 4;
    int s = base / (LSEQ * EDIM);
    float2 st = g_stats[s];
    const float4 o = *reinterpret_cast<const float4*>(&g_o[base]);
    float4 r;
    r.x = (o.x - st.x) * st.y;
    r.y = (o.y - st.x) * st.y;
    r.z = (o.z - st.x) * st.y;
    r.w = (o.w - st.x) * st.y;
    *reinterpret_cast<float4*>(&out[base]) = r;
}

// ----------------------------------------------------------------------------
// Host launcher (graph-capturable: kernel launches + func attribute only)
// ----------------------------------------------------------------------------
extern "C" void kernel_launch(void* const* d_in, const int* in_sizes, int n_in,
                              void* d_out, int out_size)
{
    const float* info = (const float*)d_in[0];
    const float* Wq   = (const float*)d_in[1];
    const float* bq   = (const float*)d_in[2];
    const float* Wk   = (const float*)d_in[3];
    const float* bk   = (const float*)d_in[4];
    const float* Wv   = (const float*)d_in[5];
    const float* bv   = (const float*)d_in[6];
    float* out = (float*)d_out;

    const int attn_smem = (64 * 64 * 3 + 64 * KPAD) * (int)sizeof(float); // 65792
    cudaFuncSetAttribute(attn_kernel,
                         cudaFuncAttributeMaxDynamicSharedMemorySize, attn_smem);

    dim3 pgrid(LSEQ / 128, NSLICE);
    dim3 pblk(16, 16);
    proj_kernel<<<pgrid, pblk>>>(info, Wq, bq, 0);
    proj_kernel<<<pgrid, pblk>>>(info, Wk, bk, 1);
    proj_kernel<<<pgrid, pblk>>>(info, Wv, bv, 2);

    dim3 agrid(LSEQ / 64, NSLICE);
    attn_kernel<<<agrid, pblk, attn_smem>>>();

    stats_kernel<<<NSLICE, 32>>>();

    int total4 = NSLICE * LSEQ * EDIM / 4;          // 524288
    norm_kernel<<<total4 / 256, 256>>>(out);
}